// round 13
// baseline (speedup 1.0000x reference)
#include <cuda_runtime.h>
#include <cuda_bf16.h>
#include <cstdint>
#include <math.h>

#define TOK    8192
#define DMODEL 1024
#define NSEQ   1024
#define NHEAD  16
#define DHEAD  64
#define QKVN   3072

// ---------------- scratch (static device globals) -------------------------
__device__ __nv_bfloat16 g_zn_hi[TOK * DMODEL];
__device__ __nv_bfloat16 g_zn_lo[TOK * DMODEL];
__device__ __nv_bfloat16 g_wq_hi[QKVN * DMODEL];   // W_qkv^T hi  [N,K]
__device__ __nv_bfloat16 g_wq_lo[QKVN * DMODEL];
__device__ __nv_bfloat16 g_wp_hi[DMODEL * DMODEL]; // W_proj^T hi [N,K]
__device__ __nv_bfloat16 g_wp_lo[DMODEL * DMODEL];
__device__ __nv_bfloat16 g_qkv_hi[TOK * QKVN];
__device__ __nv_bfloat16 g_qkv_lo[TOK * QKVN];
__device__ __nv_bfloat16 g_msa_hi[TOK * DMODEL];
__device__ __nv_bfloat16 g_msa_lo[TOK * DMODEL];

// ---------------- PTX helpers ----------------------------------------------
__device__ __forceinline__ uint32_t smem_u32(const void* p) {
    uint32_t a;
    asm("{ .reg .u64 t; cvta.to.shared.u64 t, %1; cvt.u32.u64 %0, t; }"
        : "=r"(a) : "l"(p));
    return a;
}
__device__ __forceinline__ void cp16(uint32_t dst, const void* src) {
    size_t g = __cvta_generic_to_global(src);
    asm volatile("cp.async.cg.shared.global [%0], [%1], 16;" :: "r"(dst), "l"(g));
}
__device__ __forceinline__ void ldsm4(uint32_t* r, uint32_t addr) {
    asm volatile("ldmatrix.sync.aligned.m8n8.x4.shared.b16 {%0,%1,%2,%3}, [%4];"
        : "=r"(r[0]), "=r"(r[1]), "=r"(r[2]), "=r"(r[3]) : "r"(addr));
}
__device__ __forceinline__ void ldsm4t(uint32_t* r, uint32_t addr) {
    asm volatile("ldmatrix.sync.aligned.m8n8.x4.trans.shared.b16 {%0,%1,%2,%3}, [%4];"
        : "=r"(r[0]), "=r"(r[1]), "=r"(r[2]), "=r"(r[3]) : "r"(addr));
}
__device__ __forceinline__ void mma16816(float* d, const uint32_t* a,
                                         uint32_t b0, uint32_t b1) {
    asm volatile("mma.sync.aligned.m16n8k16.row.col.f32.bf16.bf16.f32 "
        "{%0,%1,%2,%3}, {%4,%5,%6,%7}, {%8,%9}, {%0,%1,%2,%3};"
        : "+f"(d[0]), "+f"(d[1]), "+f"(d[2]), "+f"(d[3])
        : "r"(a[0]), "r"(a[1]), "r"(a[2]), "r"(a[3]), "r"(b0), "r"(b1));
}
__device__ __forceinline__ void split_bf16(float x, __nv_bfloat16& h, __nv_bfloat16& l) {
    h = __float2bfloat16(x);
    l = __float2bfloat16(x - __bfloat162float(h));
}
__device__ __forceinline__ uint32_t pack_split(float a, float b, uint32_t& lo_out) {
    __nv_bfloat16 ha, la, hb, lb;
    split_bf16(a, ha, la);
    split_bf16(b, hb, lb);
    __nv_bfloat162 h2 = __halves2bfloat162(ha, hb);
    __nv_bfloat162 l2 = __halves2bfloat162(la, lb);
    lo_out = *reinterpret_cast<uint32_t*>(&l2);
    return *reinterpret_cast<uint32_t*>(&h2);
}

// ---------------- LayerNorm -> bf16 hi/lo ---------------------------------
__global__ void __launch_bounds__(256) ln_kernel(
    const float* __restrict__ z, const float* __restrict__ w,
    const float* __restrict__ bias,
    __nv_bfloat16* __restrict__ oh, __nv_bfloat16* __restrict__ ol)
{
    int row = blockIdx.x;
    int t   = threadIdx.x;
    const float4* zr = reinterpret_cast<const float4*>(z + (size_t)row * DMODEL);
    float4 x = zr[t];
    float s  = x.x + x.y + x.z + x.w;
    float s2 = x.x*x.x + x.y*x.y + x.z*x.z + x.w*x.w;
    #pragma unroll
    for (int o = 16; o > 0; o >>= 1) {
        s  += __shfl_xor_sync(0xffffffffu, s,  o);
        s2 += __shfl_xor_sync(0xffffffffu, s2, o);
    }
    __shared__ float red[16];
    int warp = t >> 5, lane = t & 31;
    if (lane == 0) { red[warp] = s; red[8 + warp] = s2; }
    __syncthreads();
    float ts = 0.f, ts2 = 0.f;
    #pragma unroll
    for (int i = 0; i < 8; i++) { ts += red[i]; ts2 += red[8 + i]; }
    float mu  = ts * (1.0f / DMODEL);
    float var = ts2 * (1.0f / DMODEL) - mu * mu;
    float rstd = rsqrtf(var + 1e-5f);
    const float4* w4 = reinterpret_cast<const float4*>(w);
    const float4* b4 = reinterpret_cast<const float4*>(bias);
    float4 ww = w4[t], bb = b4[t];
    float v[4];
    v[0] = (x.x - mu) * rstd * ww.x + bb.x;
    v[1] = (x.y - mu) * rstd * ww.y + bb.y;
    v[2] = (x.z - mu) * rstd * ww.z + bb.z;
    v[3] = (x.w - mu) * rstd * ww.w + bb.w;
    size_t o = (size_t)row * DMODEL + t * 4;
    uint32_t l01, l23;
    uint32_t h01 = pack_split(v[0], v[1], l01);
    uint32_t h23 = pack_split(v[2], v[3], l23);
    *reinterpret_cast<uint32_t*>(oh + o)     = h01;
    *reinterpret_cast<uint32_t*>(oh + o + 2) = h23;
    *reinterpret_cast<uint32_t*>(ol + o)     = l01;
    *reinterpret_cast<uint32_t*>(ol + o + 2) = l23;
}

// ---------------- W[K,N] -> W^T[N,K] bf16 hi/lo ----------------------------
__global__ void __launch_bounds__(256) wsplit_t(
    const float* __restrict__ W, __nv_bfloat16* __restrict__ Th,
    __nv_bfloat16* __restrict__ Tl, int Kd, int Nd)
{
    __shared__ float t[32][33];
    int n0 = blockIdx.x * 32, k0 = blockIdx.y * 32;
    int tx = threadIdx.x, ty0 = threadIdx.y;  // (32,8)
    for (int i = ty0; i < 32; i += 8)
        t[i][tx] = W[(size_t)(k0 + i) * Nd + n0 + tx];
    __syncthreads();
    for (int i = ty0; i < 32; i += 8) {
        float v = t[tx][i];                  // = W[k0+tx][n0+i]
        __nv_bfloat16 h, l;
        split_bf16(v, h, l);
        size_t o = (size_t)(n0 + i) * Kd + k0 + tx;
        Th[o] = h; Tl[o] = l;
    }
}

// ---------------- HMMA GEMM: 128x128 CTA, 8 warps of 64x32, BK=32 ----------
// 3-stage cp.async pipeline, one __syncthreads per chunk, 2 CTAs/SM.
// Term-major MMA ordering: dependent MMAs on the same accumulator are 16 apart.
// Smem: unpadded 64B rows, XOR swizzle byte(row,seg)=row*64+((seg^((row>>1)&3))<<4)
#define BK     32
#define ARR    (128 * 64)               // 8192 B per array
#define STG    (4 * ARR)                // 32768 B per stage
#define NSTAGE 3
#define GEMM_SMEM (NSTAGE * STG)        // 98304 B -> 2 CTAs/SM

template <int MODE>
__global__ void __launch_bounds__(256, 2) gemm_mma(
    const __nv_bfloat16* __restrict__ Ahi, const __nv_bfloat16* __restrict__ Alo,
    const __nv_bfloat16* __restrict__ Bhi, const __nv_bfloat16* __restrict__ Blo,
    const float* __restrict__ bias, const float* __restrict__ R,
    float* __restrict__ C,
    __nv_bfloat16* __restrict__ Ch, __nv_bfloat16* __restrict__ Cl, int N)
{
    extern __shared__ char smem[];
    uint32_t sb = smem_u32(smem);
    int tid = threadIdx.x, lane = tid & 31, wid = tid >> 5;
    int wm = wid >> 2, wn = wid & 3;            // 2 x 4 warp grid, 64x32 tiles
    int brow = blockIdx.y * 128, bcol = blockIdx.x * 128;

    float acc[4][4][4];
    #pragma unroll
    for (int i = 0; i < 4; i++)
        #pragma unroll
        for (int j = 0; j < 4; j++)
            #pragma unroll
            for (int k = 0; k < 4; k++) acc[i][j][k] = 0.f;

    int l_row = tid >> 1;                        // 0..127 (two segs per thread)
    int l_seg = (tid & 1) * 2;                   // 0 or 2
    auto load_chunk = [&](int c, int s) {
        uint32_t base = sb + s * STG;
        int k0 = c * BK;
        int sw = (l_row >> 1) & 3;
        uint32_t d0 = (uint32_t)(l_row * 64 + (((l_seg + 0) ^ sw) << 4));
        uint32_t d1 = (uint32_t)(l_row * 64 + (((l_seg + 1) ^ sw) << 4));
        size_t aoff = (size_t)(brow + l_row) * DMODEL + k0 + l_seg * 8;
        size_t boff = (size_t)(bcol + l_row) * DMODEL + k0 + l_seg * 8;
        cp16(base + 0 * ARR + d0, Ahi + aoff);
        cp16(base + 0 * ARR + d1, Ahi + aoff + 8);
        cp16(base + 1 * ARR + d0, Alo + aoff);
        cp16(base + 1 * ARR + d1, Alo + aoff + 8);
        cp16(base + 2 * ARR + d0, Bhi + boff);
        cp16(base + 2 * ARR + d1, Bhi + boff + 8);
        cp16(base + 3 * ARR + d0, Blo + boff);
        cp16(base + 3 * ARR + d1, Blo + boff + 8);
        asm volatile("cp.async.commit_group;" ::: "memory");
    };

    // prologue: 2 chunks in flight
    load_chunk(0, 0);
    load_chunk(1, 1);

    int a_row = wm * 64 + (lane & 15);          // + mi*16
    int a_ks  = lane >> 4;                      // 16B-seg within k-half
    int b_row = wn * 32 + (lane >> 4) * 8 + (lane & 7);  // + p*16
    int b_ks  = (lane >> 3) & 1;

    const int NCH = DMODEL / BK;                 // 32
    int stage = 0;                               // = c % 3
    for (int c = 0; c < NCH; c++) {
        if (c < NCH - 1) asm volatile("cp.async.wait_group 1;" ::: "memory");
        else             asm volatile("cp.async.wait_group 0;" ::: "memory");
        __syncthreads();
        if (c + 2 < NCH) {
            int ns = stage + 2; if (ns >= 3) ns -= 3;
            load_chunk(c + 2, ns);
        }

        uint32_t base = sb + stage * STG;
        #pragma unroll
        for (int ks = 0; ks < 2; ks++) {
            uint32_t ah[4][4], al[4][4], bh[2][4], bl[2][4];
            #pragma unroll
            for (int mi = 0; mi < 4; mi++) {
                int r = a_row + mi * 16;
                uint32_t off = (uint32_t)(r * 64 +
                    (((ks * 2 + a_ks) ^ ((r >> 1) & 3)) << 4));
                ldsm4(ah[mi], base + 0 * ARR + off);
                ldsm4(al[mi], base + 1 * ARR + off);
            }
            #pragma unroll
            for (int p = 0; p < 2; p++) {
                int r = b_row + p * 16;
                uint32_t off = (uint32_t)(r * 64 +
                    (((ks * 2 + b_ks) ^ ((r >> 1) & 3)) << 4));
                ldsm4(bh[p], base + 2 * ARR + off);
                ldsm4(bl[p], base + 3 * ARR + off);
            }
            // term-major: all 16 tiles per term; dependent MMAs 16 apart
            #pragma unroll
            for (int mi = 0; mi < 4; mi++)
                #pragma unroll
                for (int ni = 0; ni < 4; ni++)
                    mma16816(acc[mi][ni], ah[mi],
                             bh[ni >> 1][(ni & 1) * 2], bh[ni >> 1][(ni & 1) * 2 + 1]);
            #pragma unroll
            for (int mi = 0; mi < 4; mi++)
                #pragma unroll
                for (int ni = 0; ni < 4; ni++)
                    mma16816(acc[mi][ni], al[mi],
                             bh[ni >> 1][(ni & 1) * 2], bh[ni >> 1][(ni & 1) * 2 + 1]);
            #pragma unroll
            for (int mi = 0; mi < 4; mi++)
                #pragma unroll
                for (int ni = 0; ni < 4; ni++)
                    mma16816(acc[mi][ni], ah[mi],
                             bl[ni >> 1][(ni & 1) * 2], bl[ni >> 1][(ni & 1) * 2 + 1]);
        }
        stage++; if (stage >= 3) stage = 0;
    }

    int gid = lane >> 2, tig = lane & 3;
    #pragma unroll
    for (int mi = 0; mi < 4; mi++) {
        int row0 = brow + wm * 64 + mi * 16 + gid;
        #pragma unroll
        for (int ni = 0; ni < 4; ni++) {
            int col = bcol + wn * 32 + ni * 8 + tig * 2;
            float b0 = bias[col], b1 = bias[col + 1];
            #pragma unroll
            for (int h = 0; h < 2; h++) {
                int row = row0 + h * 8;
                size_t off = (size_t)row * N + col;
                float ox = acc[mi][ni][2 * h + 0] + b0;
                float oy = acc[mi][ni][2 * h + 1] + b1;
                if (MODE == 1) {
                    float2 r = *reinterpret_cast<const float2*>(R + off);
                    float2 o; o.x = ox + r.x; o.y = oy + r.y;
                    *reinterpret_cast<float2*>(C + off) = o;
                } else {
                    uint32_t lo;
                    uint32_t hi = pack_split(ox, oy, lo);
                    *reinterpret_cast<uint32_t*>(Ch + off) = hi;
                    *reinterpret_cast<uint32_t*>(Cl + off) = lo;
                }
            }
        }
    }
}

// ---------------- HMMA flash attention (term-major MMA ordering) -----------
// CTA: 128 q rows x 16 key-tiles of 64. 8 warps x 16 q-rows.
#define ASTR 72
#define ATTN_SMEM (36864 * 3)

__global__ void __launch_bounds__(256) attn_mma(
    const __nv_bfloat16* __restrict__ qg_h, const __nv_bfloat16* __restrict__ qg_l,
    __nv_bfloat16* __restrict__ msa_hi, __nv_bfloat16* __restrict__ msa_lo)
{
    extern __shared__ char smc[];
    uint32_t sb = smem_u32(smc);
    int tid = threadIdx.x, lane = tid & 31, wid = tid >> 5;
    int qt = blockIdx.x, bh = blockIdx.y;
    int b = bh >> 4, h = bh & 15;

    size_t qbase = ((size_t)(b * NSEQ + qt * 128)) * QKVN + h * DHEAD;
    size_t kbase = ((size_t)(b * NSEQ)) * QKVN + DMODEL + h * DHEAD;
    size_t vbase = kbase + DMODEL;

    // ---- Q tile load (group 0) ----
    #pragma unroll
    for (int i = 0; i < 8; i++) {
        int idx = tid + i * 256;            // 0..2047
        int arr = idx >> 10;                // 0 hi, 1 lo
        int rem = idx & 1023;
        int row = rem >> 3, seg = rem & 7;
        uint32_t d = sb + arr * 18432 + (uint32_t)(row * ASTR + seg * 8) * 2;
        const __nv_bfloat16* src = (arr ? qg_l : qg_h) + qbase + (size_t)row * QKVN + seg * 8;
        cp16(d, src);
    }
    asm volatile("cp.async.commit_group;" ::: "memory");

    auto load_kv = [&](int t, int s) {
        uint32_t stg = sb + 36864 + s * 36864;
        size_t kb = kbase + (size_t)t * 64 * QKVN;
        size_t vb = vbase + (size_t)t * 64 * QKVN;
        #pragma unroll
        for (int i = 0; i < 8; i++) {
            int idx = tid + i * 256;        // 0..2047
            int arr = idx >> 9;             // 0 Kh,1 Kl,2 Vh,3 Vl
            int rem = idx & 511;
            int row = rem >> 3, seg = rem & 7;
            uint32_t d = stg + arr * 9216 + (uint32_t)(row * ASTR + seg * 8) * 2;
            size_t off = (size_t)row * QKVN + seg * 8;
            const __nv_bfloat16* src;
            if      (arr == 0) src = qg_h + kb + off;
            else if (arr == 1) src = qg_l + kb + off;
            else if (arr == 2) src = qg_h + vb + off;
            else               src = qg_l + vb + off;
            cp16(d, src);
        }
        asm volatile("cp.async.commit_group;" ::: "memory");
    };
    load_kv(0, 0);
    load_kv(1, 1);

    // ---- wait Q; load Q fragments to registers (scaled by 1/8) ----
    asm volatile("cp.async.wait_group 2;" ::: "memory");
    __syncthreads();
    uint32_t qh[4][4], ql[4][4];
    {
        int row = wid * 16 + (lane & 15);
        int kc  = (lane >> 4) * 8;
        #pragma unroll
        for (int ks = 0; ks < 4; ks++) {
            uint32_t off = (uint32_t)((row * ASTR + ks * 16 + kc) * 2);
            ldsm4(qh[ks], sb + off);
            ldsm4(ql[ks], sb + 18432 + off);
        }
        __nv_bfloat162 sc = __float2bfloat162_rn(0.125f);
        #pragma unroll
        for (int ks = 0; ks < 4; ks++)
            #pragma unroll
            for (int r = 0; r < 4; r++) {
                __nv_bfloat162 vh = *reinterpret_cast<__nv_bfloat162*>(&qh[ks][r]);
                __nv_bfloat162 vl = *reinterpret_cast<__nv_bfloat162*>(&ql[ks][r]);
                vh = __hmul2(vh, sc);
                vl = __hmul2(vl, sc);
                qh[ks][r] = *reinterpret_cast<uint32_t*>(&vh);
                ql[ks][r] = *reinterpret_cast<uint32_t*>(&vl);
            }
    }

    float m0 = -1e30f, m1 = -1e30f, l0 = 0.f, l1 = 0.f;
    float oacc[8][4];
    #pragma unroll
    for (int i = 0; i < 8; i++)
        #pragma unroll
        for (int j = 0; j < 4; j++) oacc[i][j] = 0.f;

    int krow = (lane >> 4) * 8 + (lane & 7);     // + p*16
    int kc2  = ((lane >> 3) & 1) * 8;            // + ks*16
    int vkey = ((lane >> 3) & 1) * 8 + (lane & 7);   // + ks*16
    int vdh  = ((lane >> 4) & 1) * 8;            // + p*16

    for (int t = 0; t < 16; t++) {
        if (t < 15) asm volatile("cp.async.wait_group 1;" ::: "memory");
        else        asm volatile("cp.async.wait_group 0;" ::: "memory");
        __syncthreads();
        uint32_t stg = sb + 36864 + (t & 1) * 36864;

        // ---- S = Q K^T (term-major: dependent MMAs 8 apart) ----
        float sacc[8][4];
        #pragma unroll
        for (int i = 0; i < 8; i++)
            #pragma unroll
            for (int j = 0; j < 4; j++) sacc[i][j] = 0.f;

        #pragma unroll
        for (int ks = 0; ks < 4; ks++) {
            uint32_t kh[4][4], kl[4][4];
            #pragma unroll
            for (int p = 0; p < 4; p++) {
                uint32_t off = (uint32_t)(((p * 16 + krow) * ASTR + ks * 16 + kc2) * 2);
                ldsm4(kh[p], stg + off);
                ldsm4(kl[p], stg + 9216 + off);
            }
            #pragma unroll
            for (int nt = 0; nt < 8; nt++)
                mma16816(sacc[nt], qh[ks],
                         kh[nt >> 1][(nt & 1) * 2], kh[nt >> 1][(nt & 1) * 2 + 1]);
            #pragma unroll
            for (int nt = 0; nt < 8; nt++)
                mma16816(sacc[nt], ql[ks],
                         kh[nt >> 1][(nt & 1) * 2], kh[nt >> 1][(nt & 1) * 2 + 1]);
            #pragma unroll
            for (int nt = 0; nt < 8; nt++)
                mma16816(sacc[nt], qh[ks],
                         kl[nt >> 1][(nt & 1) * 2], kl[nt >> 1][(nt & 1) * 2 + 1]);
        }

        // ---- online softmax ----
        float mx0 = -1e30f, mx1 = -1e30f;
        #pragma unroll
        for (int nt = 0; nt < 8; nt++) {
            mx0 = fmaxf(mx0, fmaxf(sacc[nt][0], sacc[nt][1]));
            mx1 = fmaxf(mx1, fmaxf(sacc[nt][2], sacc[nt][3]));
        }
        mx0 = fmaxf(mx0, __shfl_xor_sync(0xffffffffu, mx0, 1));
        mx0 = fmaxf(mx0, __shfl_xor_sync(0xffffffffu, mx0, 2));
        mx1 = fmaxf(mx1, __shfl_xor_sync(0xffffffffu, mx1, 1));
        mx1 = fmaxf(mx1, __shfl_xor_sync(0xffffffffu, mx1, 2));
        float mn0 = fmaxf(m0, mx0), mn1 = fmaxf(m1, mx1);
        float f0 = __expf(m0 - mn0), f1 = __expf(m1 - mn1);
        m0 = mn0; m1 = mn1;

        float s0 = 0.f, s1 = 0.f;
        uint32_t phi[8][2], plo[8][2];
        #pragma unroll
        for (int nt = 0; nt < 8; nt++) {
            float e0 = __expf(sacc[nt][0] - mn0);
            float e1 = __expf(sacc[nt][1] - mn0);
            float e2 = __expf(sacc[nt][2] - mn1);
            float e3 = __expf(sacc[nt][3] - mn1);
            s0 += e0 + e1; s1 += e2 + e3;
            phi[nt][0] = pack_split(e0, e1, plo[nt][0]);
            phi[nt][1] = pack_split(e2, e3, plo[nt][1]);
        }
        s0 += __shfl_xor_sync(0xffffffffu, s0, 1);
        s0 += __shfl_xor_sync(0xffffffffu, s0, 2);
        s1 += __shfl_xor_sync(0xffffffffu, s1, 1);
        s1 += __shfl_xor_sync(0xffffffffu, s1, 2);
        l0 = l0 * f0 + s0;
        l1 = l1 * f1 + s1;
        #pragma unroll
        for (int nt = 0; nt < 8; nt++) {
            oacc[nt][0] *= f0; oacc[nt][1] *= f0;
            oacc[nt][2] *= f1; oacc[nt][3] *= f1;
        }

        // ---- O += P V (term-major) ----
        #pragma unroll
        for (int ks = 0; ks < 4; ks++) {
            uint32_t pah[4] = { phi[2*ks][0], phi[2*ks][1], phi[2*ks+1][0], phi[2*ks+1][1] };
            uint32_t pal[4] = { plo[2*ks][0], plo[2*ks][1], plo[2*ks+1][0], plo[2*ks+1][1] };
            uint32_t vh[4][4], vl[4][4];
            #pragma unroll
            for (int p = 0; p < 4; p++) {
                uint32_t off = (uint32_t)(((ks * 16 + vkey) * ASTR + p * 16 + vdh) * 2);
                ldsm4t(vh[p], stg + 18432 + off);
                ldsm4t(vl[p], stg + 27648 + off);
            }
            #pragma unroll
            for (int nt = 0; nt < 8; nt++)
                mma16816(oacc[nt], pah,
                         vh[nt >> 1][(nt & 1) * 2], vh[nt >> 1][(nt & 1) * 2 + 1]);
            #pragma unroll
            for (int nt = 0; nt < 8; nt++)
                mma16816(oacc[nt], pal,
                         vh[nt >> 1][(nt & 1) * 2], vh[nt >> 1][(nt & 1) * 2 + 1]);
            #pragma unroll
            for (int nt = 0; nt < 8; nt++)
                mma16816(oacc[nt], pah,
                         vl[nt >> 1][(nt & 1) * 2], vl[nt >> 1][(nt & 1) * 2 + 1]);
        }
        __syncthreads();
        if (t + 2 < 16) load_kv(t + 2, t & 1);
    }

    // ---- epilogue ----
    float inv0 = 1.f / l0, inv1 = 1.f / l1;
    size_t tok0 = (size_t)(b * NSEQ + qt * 128 + wid * 16 + (lane >> 2));
    int colb = h * DHEAD + (lane & 3) * 2;
    #pragma unroll
    for (int nt = 0; nt < 8; nt++) {
        int col = colb + nt * 8;
        uint32_t lo;
        uint32_t hi = pack_split(oacc[nt][0] * inv0, oacc[nt][1] * inv0, lo);
        size_t off0 = tok0 * DMODEL + col;
        *reinterpret_cast<uint32_t*>(msa_hi + off0) = hi;
        *reinterpret_cast<uint32_t*>(msa_lo + off0) = lo;
        hi = pack_split(oacc[nt][2] * inv1, oacc[nt][3] * inv1, lo);
        size_t off1 = (tok0 + 8) * DMODEL + col;
        *reinterpret_cast<uint32_t*>(msa_hi + off1) = hi;
        *reinterpret_cast<uint32_t*>(msa_lo + off1) = lo;
    }
}

// ---------------- launch --------------------------------------------------
extern "C" void kernel_launch(void* const* d_in, const int* in_sizes, int n_in,
                              void* d_out, int out_size)
{
    const float* z      = (const float*)d_in[0];
    const float* ln_w   = (const float*)d_in[1];
    const float* ln_b   = (const float*)d_in[2];
    const float* W_qkv  = (const float*)d_in[3];
    const float* b_qkv  = (const float*)d_in[4];
    const float* W_proj = (const float*)d_in[5];
    const float* b_proj = (const float*)d_in[6];
    float* out = (float*)d_out;

    __nv_bfloat16 *p_znh, *p_znl, *p_wqh, *p_wql, *p_wph, *p_wpl;
    __nv_bfloat16 *p_qh, *p_ql, *p_mh, *p_ml;
    cudaGetSymbolAddress((void**)&p_znh, g_zn_hi);
    cudaGetSymbolAddress((void**)&p_znl, g_zn_lo);
    cudaGetSymbolAddress((void**)&p_wqh, g_wq_hi);
    cudaGetSymbolAddress((void**)&p_wql, g_wq_lo);
    cudaGetSymbolAddress((void**)&p_wph, g_wp_hi);
    cudaGetSymbolAddress((void**)&p_wpl, g_wp_lo);
    cudaGetSymbolAddress((void**)&p_qh,  g_qkv_hi);
    cudaGetSymbolAddress((void**)&p_ql,  g_qkv_lo);
    cudaGetSymbolAddress((void**)&p_mh,  g_msa_hi);
    cudaGetSymbolAddress((void**)&p_ml,  g_msa_lo);

    cudaFuncSetAttribute(gemm_mma<0>, cudaFuncAttributeMaxDynamicSharedMemorySize, GEMM_SMEM);
    cudaFuncSetAttribute(gemm_mma<1>, cudaFuncAttributeMaxDynamicSharedMemorySize, GEMM_SMEM);
    cudaFuncSetAttribute(attn_mma, cudaFuncAttributeMaxDynamicSharedMemorySize, ATTN_SMEM);

    // 1) LayerNorm -> zn hi/lo
    ln_kernel<<<TOK, 256>>>(z, ln_w, ln_b, p_znh, p_znl);

    // 2) weight transpose + split
    wsplit_t<<<dim3(QKVN / 32, DMODEL / 32), dim3(32, 8)>>>(W_qkv, p_wqh, p_wql, DMODEL, QKVN);
    wsplit_t<<<dim3(DMODEL / 32, DMODEL / 32), dim3(32, 8)>>>(W_proj, p_wph, p_wpl, DMODEL, DMODEL);

    // 3) QKV projection -> bf16 hi/lo qkv
    gemm_mma<0><<<dim3(QKVN / 128, TOK / 128), 256, GEMM_SMEM>>>(
        p_znh, p_znl, p_wqh, p_wql, b_qkv, nullptr, nullptr, p_qh, p_ql, QKVN);

    // 4) attention (HMMA) -> msa hi/lo
    attn_mma<<<dim3(NSEQ / 128, 8 * NHEAD), 256, ATTN_SMEM>>>(p_qh, p_ql, p_mh, p_ml);

    // 5) output projection + bias + residual
    gemm_mma<1><<<dim3(DMODEL / 128, TOK / 128), 256, GEMM_SMEM>>>(
        p_mh, p_ml, p_wph, p_wpl, b_proj, z, out, nullptr, nullptr, DMODEL);
}

// round 17
// speedup vs baseline: 1.3196x; 1.3196x over previous
#include <cuda_runtime.h>
#include <cuda_bf16.h>
#include <cuda_fp16.h>
#include <cstdint>
#include <math.h>

#define TOK    8192
#define DMODEL 1024
#define NSEQ   1024
#define NHEAD  16
#define DHEAD  64
#define QKVN   3072

// ---------------- scratch (static device globals) -------------------------
__device__ __nv_bfloat16 g_zn_hi[TOK * DMODEL];
__device__ __nv_bfloat16 g_zn_lo[TOK * DMODEL];
__device__ __nv_bfloat16 g_wq_hi[QKVN * DMODEL];   // W_qkv^T hi  [N,K]
__device__ __nv_bfloat16 g_wq_lo[QKVN * DMODEL];
__device__ __nv_bfloat16 g_wp_hi[DMODEL * DMODEL]; // W_proj^T hi [N,K]
__device__ __nv_bfloat16 g_wp_lo[DMODEL * DMODEL];
__device__ __half        g_qkv16[TOK * QKVN];      // fp16 qkv for attention
__device__ __nv_bfloat16 g_msa_hi[TOK * DMODEL];
__device__ __nv_bfloat16 g_msa_lo[TOK * DMODEL];

// ---------------- PTX helpers ----------------------------------------------
__device__ __forceinline__ uint32_t smem_u32(const void* p) {
    uint32_t a;
    asm("{ .reg .u64 t; cvta.to.shared.u64 t, %1; cvt.u32.u64 %0, t; }"
        : "=r"(a) : "l"(p));
    return a;
}
__device__ __forceinline__ void cp16(uint32_t dst, const void* src) {
    size_t g = __cvta_generic_to_global(src);
    asm volatile("cp.async.cg.shared.global [%0], [%1], 16;" :: "r"(dst), "l"(g));
}
__device__ __forceinline__ void ldsm4(uint32_t* r, uint32_t addr) {
    asm volatile("ldmatrix.sync.aligned.m8n8.x4.shared.b16 {%0,%1,%2,%3}, [%4];"
        : "=r"(r[0]), "=r"(r[1]), "=r"(r[2]), "=r"(r[3]) : "r"(addr));
}
__device__ __forceinline__ void ldsm4t(uint32_t* r, uint32_t addr) {
    asm volatile("ldmatrix.sync.aligned.m8n8.x4.trans.shared.b16 {%0,%1,%2,%3}, [%4];"
        : "=r"(r[0]), "=r"(r[1]), "=r"(r[2]), "=r"(r[3]) : "r"(addr));
}
__device__ __forceinline__ void mma16816(float* d, const uint32_t* a,
                                         uint32_t b0, uint32_t b1) {
    asm volatile("mma.sync.aligned.m16n8k16.row.col.f32.bf16.bf16.f32 "
        "{%0,%1,%2,%3}, {%4,%5,%6,%7}, {%8,%9}, {%0,%1,%2,%3};"
        : "+f"(d[0]), "+f"(d[1]), "+f"(d[2]), "+f"(d[3])
        : "r"(a[0]), "r"(a[1]), "r"(a[2]), "r"(a[3]), "r"(b0), "r"(b1));
}
__device__ __forceinline__ void mma16816h(float* d, const uint32_t* a,
                                          uint32_t b0, uint32_t b1) {
    asm volatile("mma.sync.aligned.m16n8k16.row.col.f32.f16.f16.f32 "
        "{%0,%1,%2,%3}, {%4,%5,%6,%7}, {%8,%9}, {%0,%1,%2,%3};"
        : "+f"(d[0]), "+f"(d[1]), "+f"(d[2]), "+f"(d[3])
        : "r"(a[0]), "r"(a[1]), "r"(a[2]), "r"(a[3]), "r"(b0), "r"(b1));
}
__device__ __forceinline__ void split_bf16(float x, __nv_bfloat16& h, __nv_bfloat16& l) {
    h = __float2bfloat16(x);
    l = __float2bfloat16(x - __bfloat162float(h));
}
__device__ __forceinline__ uint32_t pack_split(float a, float b, uint32_t& lo_out) {
    __nv_bfloat16 ha, la, hb, lb;
    split_bf16(a, ha, la);
    split_bf16(b, hb, lb);
    __nv_bfloat162 h2 = __halves2bfloat162(ha, hb);
    __nv_bfloat162 l2 = __halves2bfloat162(la, lb);
    lo_out = *reinterpret_cast<uint32_t*>(&l2);
    return *reinterpret_cast<uint32_t*>(&h2);
}
__device__ __forceinline__ uint32_t pack_h2(float a, float b) {
    __half2 h = __floats2half2_rn(a, b);
    return *reinterpret_cast<uint32_t*>(&h);
}

// ---------------- LayerNorm -> bf16 hi/lo ---------------------------------
__global__ void __launch_bounds__(256) ln_kernel(
    const float* __restrict__ z, const float* __restrict__ w,
    const float* __restrict__ bias,
    __nv_bfloat16* __restrict__ oh, __nv_bfloat16* __restrict__ ol)
{
    int row = blockIdx.x;
    int t   = threadIdx.x;
    const float4* zr = reinterpret_cast<const float4*>(z + (size_t)row * DMODEL);
    float4 x = zr[t];
    float s  = x.x + x.y + x.z + x.w;
    float s2 = x.x*x.x + x.y*x.y + x.z*x.z + x.w*x.w;
    #pragma unroll
    for (int o = 16; o > 0; o >>= 1) {
        s  += __shfl_xor_sync(0xffffffffu, s,  o);
        s2 += __shfl_xor_sync(0xffffffffu, s2, o);
    }
    __shared__ float red[16];
    int warp = t >> 5, lane = t & 31;
    if (lane == 0) { red[warp] = s; red[8 + warp] = s2; }
    __syncthreads();
    float ts = 0.f, ts2 = 0.f;
    #pragma unroll
    for (int i = 0; i < 8; i++) { ts += red[i]; ts2 += red[8 + i]; }
    float mu  = ts * (1.0f / DMODEL);
    float var = ts2 * (1.0f / DMODEL) - mu * mu;
    float rstd = rsqrtf(var + 1e-5f);
    const float4* w4 = reinterpret_cast<const float4*>(w);
    const float4* b4 = reinterpret_cast<const float4*>(bias);
    float4 ww = w4[t], bb = b4[t];
    float v[4];
    v[0] = (x.x - mu) * rstd * ww.x + bb.x;
    v[1] = (x.y - mu) * rstd * ww.y + bb.y;
    v[2] = (x.z - mu) * rstd * ww.z + bb.z;
    v[3] = (x.w - mu) * rstd * ww.w + bb.w;
    size_t o = (size_t)row * DMODEL + t * 4;
    uint32_t l01, l23;
    uint32_t h01 = pack_split(v[0], v[1], l01);
    uint32_t h23 = pack_split(v[2], v[3], l23);
    *reinterpret_cast<uint32_t*>(oh + o)     = h01;
    *reinterpret_cast<uint32_t*>(oh + o + 2) = h23;
    *reinterpret_cast<uint32_t*>(ol + o)     = l01;
    *reinterpret_cast<uint32_t*>(ol + o + 2) = l23;
}

// ---------------- W[K,N] -> W^T[N,K] bf16 hi/lo ----------------------------
__global__ void __launch_bounds__(256) wsplit_t(
    const float* __restrict__ W, __nv_bfloat16* __restrict__ Th,
    __nv_bfloat16* __restrict__ Tl, int Kd, int Nd)
{
    __shared__ float t[32][33];
    int n0 = blockIdx.x * 32, k0 = blockIdx.y * 32;
    int tx = threadIdx.x, ty0 = threadIdx.y;  // (32,8)
    for (int i = ty0; i < 32; i += 8)
        t[i][tx] = W[(size_t)(k0 + i) * Nd + n0 + tx];
    __syncthreads();
    for (int i = ty0; i < 32; i += 8) {
        float v = t[tx][i];                  // = W[k0+tx][n0+i]
        __nv_bfloat16 h, l;
        split_bf16(v, h, l);
        size_t o = (size_t)(n0 + i) * Kd + k0 + tx;
        Th[o] = h; Tl[o] = l;
    }
}

// ---------------- HMMA GEMM: 128x128 CTA, 8 warps of 64x32, BK=32 ----------
// 3-stage cp.async pipeline, one __syncthreads per chunk, 2 CTAs/SM.
// MODE 0: write fp16 (H).  MODE 1: write float C = acc + bias + R.
#define BK     32
#define ARR    (128 * 64)               // 8192 B per array
#define STG    (4 * ARR)                // 32768 B per stage
#define NSTAGE 3
#define GEMM_SMEM (NSTAGE * STG)        // 98304 B -> 2 CTAs/SM

template <int MODE>
__global__ void __launch_bounds__(256, 2) gemm_mma(
    const __nv_bfloat16* __restrict__ Ahi, const __nv_bfloat16* __restrict__ Alo,
    const __nv_bfloat16* __restrict__ Bhi, const __nv_bfloat16* __restrict__ Blo,
    const float* __restrict__ bias, const float* __restrict__ R,
    float* __restrict__ C, __half* __restrict__ H, int N)
{
    extern __shared__ char smem[];
    uint32_t sb = smem_u32(smem);
    int tid = threadIdx.x, lane = tid & 31, wid = tid >> 5;
    int wm = wid >> 2, wn = wid & 3;            // 2 x 4 warp grid, 64x32 tiles
    int brow = blockIdx.y * 128, bcol = blockIdx.x * 128;

    float acc[4][4][4];
    #pragma unroll
    for (int i = 0; i < 4; i++)
        #pragma unroll
        for (int j = 0; j < 4; j++)
            #pragma unroll
            for (int k = 0; k < 4; k++) acc[i][j][k] = 0.f;

    int l_row = tid >> 1;
    int l_seg = (tid & 1) * 2;
    auto load_chunk = [&](int c, int s) {
        uint32_t base = sb + s * STG;
        int k0 = c * BK;
        int sw = (l_row >> 1) & 3;
        uint32_t d0 = (uint32_t)(l_row * 64 + (((l_seg + 0) ^ sw) << 4));
        uint32_t d1 = (uint32_t)(l_row * 64 + (((l_seg + 1) ^ sw) << 4));
        size_t aoff = (size_t)(brow + l_row) * DMODEL + k0 + l_seg * 8;
        size_t boff = (size_t)(bcol + l_row) * DMODEL + k0 + l_seg * 8;
        cp16(base + 0 * ARR + d0, Ahi + aoff);
        cp16(base + 0 * ARR + d1, Ahi + aoff + 8);
        cp16(base + 1 * ARR + d0, Alo + aoff);
        cp16(base + 1 * ARR + d1, Alo + aoff + 8);
        cp16(base + 2 * ARR + d0, Bhi + boff);
        cp16(base + 2 * ARR + d1, Bhi + boff + 8);
        cp16(base + 3 * ARR + d0, Blo + boff);
        cp16(base + 3 * ARR + d1, Blo + boff + 8);
        asm volatile("cp.async.commit_group;" ::: "memory");
    };

    load_chunk(0, 0);
    load_chunk(1, 1);

    int a_row = wm * 64 + (lane & 15);
    int a_ks  = lane >> 4;
    int b_row = wn * 32 + (lane >> 4) * 8 + (lane & 7);
    int b_ks  = (lane >> 3) & 1;

    const int NCH = DMODEL / BK;                 // 32
    int stage = 0;
    for (int c = 0; c < NCH; c++) {
        if (c < NCH - 1) asm volatile("cp.async.wait_group 1;" ::: "memory");
        else             asm volatile("cp.async.wait_group 0;" ::: "memory");
        __syncthreads();
        if (c + 2 < NCH) {
            int ns = stage + 2; if (ns >= 3) ns -= 3;
            load_chunk(c + 2, ns);
        }

        uint32_t base = sb + stage * STG;
        #pragma unroll
        for (int ks = 0; ks < 2; ks++) {
            uint32_t ah[4][4], al[4][4], bh[2][4], bl[2][4];
            #pragma unroll
            for (int mi = 0; mi < 4; mi++) {
                int r = a_row + mi * 16;
                uint32_t off = (uint32_t)(r * 64 +
                    (((ks * 2 + a_ks) ^ ((r >> 1) & 3)) << 4));
                ldsm4(ah[mi], base + 0 * ARR + off);
                ldsm4(al[mi], base + 1 * ARR + off);
            }
            #pragma unroll
            for (int p = 0; p < 2; p++) {
                int r = b_row + p * 16;
                uint32_t off = (uint32_t)(r * 64 +
                    (((ks * 2 + b_ks) ^ ((r >> 1) & 3)) << 4));
                ldsm4(bh[p], base + 2 * ARR + off);
                ldsm4(bl[p], base + 3 * ARR + off);
            }
            #pragma unroll
            for (int mi = 0; mi < 4; mi++)
                #pragma unroll
                for (int ni = 0; ni < 4; ni++) {
                    uint32_t h0 = bh[ni >> 1][(ni & 1) * 2];
                    uint32_t h1 = bh[ni >> 1][(ni & 1) * 2 + 1];
                    uint32_t l0 = bl[ni >> 1][(ni & 1) * 2];
                    uint32_t l1 = bl[ni >> 1][(ni & 1) * 2 + 1];
                    mma16816(acc[mi][ni], ah[mi], h0, h1);
                    mma16816(acc[mi][ni], al[mi], h0, h1);
                    mma16816(acc[mi][ni], ah[mi], l0, l1);
                }
        }
        stage++; if (stage >= 3) stage = 0;
    }

    int gid = lane >> 2, tig = lane & 3;
    #pragma unroll
    for (int mi = 0; mi < 4; mi++) {
        int row0 = brow + wm * 64 + mi * 16 + gid;
        #pragma unroll
        for (int ni = 0; ni < 4; ni++) {
            int col = bcol + wn * 32 + ni * 8 + tig * 2;
            float b0 = bias[col], b1 = bias[col + 1];
            #pragma unroll
            for (int h = 0; h < 2; h++) {
                int row = row0 + h * 8;
                size_t off = (size_t)row * N + col;
                float ox = acc[mi][ni][2 * h + 0] + b0;
                float oy = acc[mi][ni][2 * h + 1] + b1;
                if (MODE == 1) {
                    float2 r = *reinterpret_cast<const float2*>(R + off);
                    float2 o; o.x = ox + r.x; o.y = oy + r.y;
                    *reinterpret_cast<float2*>(C + off) = o;
                } else {
                    *reinterpret_cast<uint32_t*>(H + off) = pack_h2(ox, oy);
                }
            }
        }
    }
}

// ---------------- HMMA flash attention (fp16 single-term) ------------------
// CTA: 128 q rows x 16 key-tiles of 64. 8 warps x 16 q-rows. 2 CTAs/SM.
// smem (bytes): Q[128][72] fp16 @0 (18432); stage s @18432+s*18432:
//               K @+0 (64x72 fp16 = 9216), V @+9216
#define ASTR 72
#define QBYTES 18432
#define KVSTG  18432
#define ATTN_SMEM (QBYTES + 2 * KVSTG)   // 55296 -> 2 CTAs/SM

__global__ void __launch_bounds__(256, 2) attn_mma(
    const __half* __restrict__ qkv,
    __nv_bfloat16* __restrict__ msa_hi, __nv_bfloat16* __restrict__ msa_lo)
{
    extern __shared__ char smc[];
    uint32_t sb = smem_u32(smc);
    int tid = threadIdx.x, lane = tid & 31, wid = tid >> 5;
    int qt = blockIdx.x, bh = blockIdx.y;
    int b = bh >> 4, h = bh & 15;

    size_t qbase = ((size_t)(b * NSEQ + qt * 128)) * QKVN + h * DHEAD;
    size_t kbase = ((size_t)(b * NSEQ)) * QKVN + DMODEL + h * DHEAD;
    size_t vbase = kbase + DMODEL;

    // ---- Q tile load: 1024 cp16 over 256 threads ----
    #pragma unroll
    for (int i = 0; i < 4; i++) {
        int idx = tid + i * 256;            // 0..1023
        int row = idx >> 3, seg = idx & 7;
        uint32_t d = sb + (uint32_t)(row * ASTR + seg * 8) * 2;
        cp16(d, qkv + qbase + (size_t)row * QKVN + seg * 8);
    }
    asm volatile("cp.async.commit_group;" ::: "memory");

    auto load_kv = [&](int t, int s) {
        uint32_t stg = sb + QBYTES + s * KVSTG;
        size_t kb = kbase + (size_t)t * 64 * QKVN;
        size_t vb = vbase + (size_t)t * 64 * QKVN;
        #pragma unroll
        for (int i = 0; i < 4; i++) {
            int idx = tid + i * 256;        // 0..1023
            int arr = idx >> 9;             // 0 K, 1 V
            int rem = idx & 511;
            int row = rem >> 3, seg = rem & 7;
            uint32_t d = stg + arr * 9216 + (uint32_t)(row * ASTR + seg * 8) * 2;
            size_t off = (size_t)row * QKVN + seg * 8;
            cp16(d, qkv + (arr ? vb : kb) + off);
        }
        asm volatile("cp.async.commit_group;" ::: "memory");
    };
    load_kv(0, 0);
    load_kv(1, 1);

    // ---- wait Q; load Q fragments (scaled by 1/8, exact in fp16) ----
    asm volatile("cp.async.wait_group 2;" ::: "memory");
    __syncthreads();
    uint32_t qf[4][4];
    {
        int row = wid * 16 + (lane & 15);
        int kc  = (lane >> 4) * 8;
        #pragma unroll
        for (int ks = 0; ks < 4; ks++) {
            uint32_t off = (uint32_t)((row * ASTR + ks * 16 + kc) * 2);
            ldsm4(qf[ks], sb + off);
        }
        __half2 sc = __float2half2_rn(0.125f);
        #pragma unroll
        for (int ks = 0; ks < 4; ks++)
            #pragma unroll
            for (int r = 0; r < 4; r++) {
                __half2 v = *reinterpret_cast<__half2*>(&qf[ks][r]);
                v = __hmul2(v, sc);
                qf[ks][r] = *reinterpret_cast<uint32_t*>(&v);
            }
    }

    float m0 = -1e30f, m1 = -1e30f, l0 = 0.f, l1 = 0.f;
    float oacc[8][4];
    #pragma unroll
    for (int i = 0; i < 8; i++)
        #pragma unroll
        for (int j = 0; j < 4; j++) oacc[i][j] = 0.f;

    int krow = (lane >> 4) * 8 + (lane & 7);         // + p*16
    int kc2  = ((lane >> 3) & 1) * 8;                // + ks*16
    int vkey = ((lane >> 3) & 1) * 8 + (lane & 7);   // + ks*16
    int vdh  = ((lane >> 4) & 1) * 8;                // + p*16

    for (int t = 0; t < 16; t++) {
        if (t < 15) asm volatile("cp.async.wait_group 1;" ::: "memory");
        else        asm volatile("cp.async.wait_group 0;" ::: "memory");
        __syncthreads();
        uint32_t stg = sb + QBYTES + (t & 1) * KVSTG;

        // ---- S = Q K^T ----
        float sacc[8][4];
        #pragma unroll
        for (int i = 0; i < 8; i++)
            #pragma unroll
            for (int j = 0; j < 4; j++) sacc[i][j] = 0.f;

        #pragma unroll
        for (int ks = 0; ks < 4; ks++) {
            uint32_t kf[4][4];
            #pragma unroll
            for (int p = 0; p < 4; p++) {
                uint32_t off = (uint32_t)(((p * 16 + krow) * ASTR + ks * 16 + kc2) * 2);
                ldsm4(kf[p], stg + off);
            }
            #pragma unroll
            for (int nt = 0; nt < 8; nt++)
                mma16816h(sacc[nt], qf[ks],
                          kf[nt >> 1][(nt & 1) * 2], kf[nt >> 1][(nt & 1) * 2 + 1]);
        }

        // ---- online softmax ----
        float mx0 = -1e30f, mx1 = -1e30f;
        #pragma unroll
        for (int nt = 0; nt < 8; nt++) {
            mx0 = fmaxf(mx0, fmaxf(sacc[nt][0], sacc[nt][1]));
            mx1 = fmaxf(mx1, fmaxf(sacc[nt][2], sacc[nt][3]));
        }
        mx0 = fmaxf(mx0, __shfl_xor_sync(0xffffffffu, mx0, 1));
        mx0 = fmaxf(mx0, __shfl_xor_sync(0xffffffffu, mx0, 2));
        mx1 = fmaxf(mx1, __shfl_xor_sync(0xffffffffu, mx1, 1));
        mx1 = fmaxf(mx1, __shfl_xor_sync(0xffffffffu, mx1, 2));
        float mn0 = fmaxf(m0, mx0), mn1 = fmaxf(m1, mx1);
        float f0 = __expf(m0 - mn0), f1 = __expf(m1 - mn1);
        m0 = mn0; m1 = mn1;

        float s0 = 0.f, s1 = 0.f;
        uint32_t pf[8][2];
        #pragma unroll
        for (int nt = 0; nt < 8; nt++) {
            float e0 = __expf(sacc[nt][0] - mn0);
            float e1 = __expf(sacc[nt][1] - mn0);
            float e2 = __expf(sacc[nt][2] - mn1);
            float e3 = __expf(sacc[nt][3] - mn1);
            s0 += e0 + e1; s1 += e2 + e3;
            pf[nt][0] = pack_h2(e0, e1);
            pf[nt][1] = pack_h2(e2, e3);
        }
        s0 += __shfl_xor_sync(0xffffffffu, s0, 1);
        s0 += __shfl_xor_sync(0xffffffffu, s0, 2);
        s1 += __shfl_xor_sync(0xffffffffu, s1, 1);
        s1 += __shfl_xor_sync(0xffffffffu, s1, 2);
        l0 = l0 * f0 + s0;
        l1 = l1 * f1 + s1;
        #pragma unroll
        for (int nt = 0; nt < 8; nt++) {
            oacc[nt][0] *= f0; oacc[nt][1] *= f0;
            oacc[nt][2] *= f1; oacc[nt][3] *= f1;
        }

        // ---- O += P V ----
        #pragma unroll
        for (int ks = 0; ks < 4; ks++) {
            uint32_t pa[4] = { pf[2*ks][0], pf[2*ks][1], pf[2*ks+1][0], pf[2*ks+1][1] };
            uint32_t vf[4][4];
            #pragma unroll
            for (int p = 0; p < 4; p++) {
                uint32_t off = (uint32_t)(((ks * 16 + vkey) * ASTR + p * 16 + vdh) * 2);
                ldsm4t(vf[p], stg + 9216 + off);
            }
            #pragma unroll
            for (int nt = 0; nt < 8; nt++)
                mma16816h(oacc[nt], pa,
                          vf[nt >> 1][(nt & 1) * 2], vf[nt >> 1][(nt & 1) * 2 + 1]);
        }
        __syncthreads();
        if (t + 2 < 16) load_kv(t + 2, t & 1);
    }

    // ---- epilogue: normalize, split, store msa hi/lo ----
    float inv0 = 1.f / l0, inv1 = 1.f / l1;
    size_t tok0 = (size_t)(b * NSEQ + qt * 128 + wid * 16 + (lane >> 2));
    int colb = h * DHEAD + (lane & 3) * 2;
    #pragma unroll
    for (int nt = 0; nt < 8; nt++) {
        int col = colb + nt * 8;
        uint32_t lo;
        uint32_t hi = pack_split(oacc[nt][0] * inv0, oacc[nt][1] * inv0, lo);
        size_t off0 = tok0 * DMODEL + col;
        *reinterpret_cast<uint32_t*>(msa_hi + off0) = hi;
        *reinterpret_cast<uint32_t*>(msa_lo + off0) = lo;
        hi = pack_split(oacc[nt][2] * inv1, oacc[nt][3] * inv1, lo);
        size_t off1 = (tok0 + 8) * DMODEL + col;
        *reinterpret_cast<uint32_t*>(msa_hi + off1) = hi;
        *reinterpret_cast<uint32_t*>(msa_lo + off1) = lo;
    }
}

// ---------------- launch --------------------------------------------------
extern "C" void kernel_launch(void* const* d_in, const int* in_sizes, int n_in,
                              void* d_out, int out_size)
{
    const float* z      = (const float*)d_in[0];
    const float* ln_w   = (const float*)d_in[1];
    const float* ln_b   = (const float*)d_in[2];
    const float* W_qkv  = (const float*)d_in[3];
    const float* b_qkv  = (const float*)d_in[4];
    const float* W_proj = (const float*)d_in[5];
    const float* b_proj = (const float*)d_in[6];
    float* out = (float*)d_out;

    __nv_bfloat16 *p_znh, *p_znl, *p_wqh, *p_wql, *p_wph, *p_wpl, *p_mh, *p_ml;
    __half *p_q16;
    cudaGetSymbolAddress((void**)&p_znh, g_zn_hi);
    cudaGetSymbolAddress((void**)&p_znl, g_zn_lo);
    cudaGetSymbolAddress((void**)&p_wqh, g_wq_hi);
    cudaGetSymbolAddress((void**)&p_wql, g_wq_lo);
    cudaGetSymbolAddress((void**)&p_wph, g_wp_hi);
    cudaGetSymbolAddress((void**)&p_wpl, g_wp_lo);
    cudaGetSymbolAddress((void**)&p_q16, g_qkv16);
    cudaGetSymbolAddress((void**)&p_mh,  g_msa_hi);
    cudaGetSymbolAddress((void**)&p_ml,  g_msa_lo);

    cudaFuncSetAttribute(gemm_mma<0>, cudaFuncAttributeMaxDynamicSharedMemorySize, GEMM_SMEM);
    cudaFuncSetAttribute(gemm_mma<1>, cudaFuncAttributeMaxDynamicSharedMemorySize, GEMM_SMEM);
    cudaFuncSetAttribute(attn_mma, cudaFuncAttributeMaxDynamicSharedMemorySize, ATTN_SMEM);

    // 1) LayerNorm -> zn hi/lo
    ln_kernel<<<TOK, 256>>>(z, ln_w, ln_b, p_znh, p_znl);

    // 2) weight transpose + split
    wsplit_t<<<dim3(QKVN / 32, DMODEL / 32), dim3(32, 8)>>>(W_qkv, p_wqh, p_wql, DMODEL, QKVN);
    wsplit_t<<<dim3(DMODEL / 32, DMODEL / 32), dim3(32, 8)>>>(W_proj, p_wph, p_wpl, DMODEL, DMODEL);

    // 3) QKV projection -> fp16 qkv
    gemm_mma<0><<<dim3(QKVN / 128, TOK / 128), 256, GEMM_SMEM>>>(
        p_znh, p_znl, p_wqh, p_wql, b_qkv, nullptr, nullptr, p_q16, QKVN);

    // 4) attention (fp16 HMMA) -> msa hi/lo
    attn_mma<<<dim3(NSEQ / 128, 8 * NHEAD), 256, ATTN_SMEM>>>(p_q16, p_mh, p_ml);

    // 5) output projection + bias + residual
    gemm_mma<1><<<dim3(DMODEL / 128, TOK / 128), 256, GEMM_SMEM>>>(
        p_mh, p_ml, p_wph, p_wpl, b_proj, z, out, nullptr, DMODEL);
}